// round 1
// baseline (speedup 1.0000x reference)
#include <cuda_runtime.h>
#include <math.h>

// Problem dims
#define BB   64
#define TT   1024
#define DD   512
#define UU   512
#define G4   2048   // 4*U
#define NOUT 4

#define RBLOCKS  128
#define RTHREADS 128

// ---------------------------------------------------------------------------
// Scratch (static device memory only — no runtime allocation)
// ---------------------------------------------------------------------------
// xz[t][col][b] : precomputed input-path activations, 1024*2048*64 fp32 = 512MB
__device__ float g_xz[(size_t)TT * G4 * BB];
// h transposed [u][b], triple buffered so one grid barrier per step suffices
__device__ float g_hT[3][UU * BB];
// grid barrier state (zero-initialized; arrive resets itself, gen is monotonic
// with != comparison, so state is valid across graph replays)
__device__ unsigned g_bar_arrive;
__device__ unsigned g_bar_gen;

// ---------------------------------------------------------------------------
// Software grid barrier. Safe because all RBLOCKS CTAs are guaranteed
// co-resident (160KB smem -> 1 CTA/SM, 128 <= 148 SMs).
// ---------------------------------------------------------------------------
__device__ __forceinline__ void grid_barrier(unsigned nb) {
    __syncthreads();
    if (threadIdx.x == 0) {
        __threadfence();                      // publish my writes
        unsigned gen = atomicAdd(&g_bar_gen, 0u);   // read phase BEFORE arriving
        if (atomicAdd(&g_bar_arrive, 1u) == nb - 1u) {
            atomicExch(&g_bar_arrive, 0u);    // reset for next barrier
            __threadfence();
            atomicAdd(&g_bar_gen, 1u);        // release
        } else {
            while (atomicAdd(&g_bar_gen, 0u) == gen) { __nanosleep(64); }
        }
        __threadfence();
    }
    __syncthreads();
}

// ---------------------------------------------------------------------------
// Kernel 1: xz[t][col][b] = sum_d tx[b][t][d] * kernel[d][col] + bias[col]
// Grid: (G4/64, TT), 256 threads. 64b x 64c tile per block, K-tiles of 32.
// ---------------------------------------------------------------------------
__global__ void __launch_bounds__(256) xz_gemm_kernel(
        const float* __restrict__ tx,
        const float* __restrict__ wk,
        const float* __restrict__ bias) {
    __shared__ float a_s[32][68];   // [kk][b], padded to 272B rows (16B aligned)
    __shared__ float w_s[32][64];   // [kk][c]

    const int t   = blockIdx.y;
    const int c0  = blockIdx.x * 64;
    const int tid = threadIdx.x;
    const int tb  = tid & 15;       // b quad
    const int tc  = tid >> 4;       // c quad

    float acc[4][4];
    #pragma unroll
    for (int i = 0; i < 4; i++)
        #pragma unroll
        for (int jj = 0; jj < 4; jj++) acc[i][jj] = 0.f;

    for (int k0 = 0; k0 < DD; k0 += 32) {
        // Load A tile (transpose into [kk][b]): global reads coalesced over kk
        {
            const int kk    = tid & 31;
            const int bbase = (tid >> 5) * 8;
            #pragma unroll
            for (int i = 0; i < 8; i++) {
                const int b = bbase + i;
                a_s[kk][b] = tx[(size_t)b * (TT * DD) + (size_t)t * DD + k0 + kk];
            }
        }
        // Load W tile [kk][c]: coalesced
        {
            #pragma unroll
            for (int i = 0; i < 8; i++) {
                const int idx = tid + i * 256;
                const int kk = idx >> 6, c = idx & 63;
                w_s[kk][c] = wk[(size_t)(k0 + kk) * G4 + c0 + c];
            }
        }
        __syncthreads();

        #pragma unroll
        for (int kk = 0; kk < 32; kk++) {
            const float4 a4 = *(const float4*)&a_s[kk][tb * 4];
            const float4 w4 = *(const float4*)&w_s[kk][tc * 4];
            acc[0][0] += a4.x * w4.x; acc[0][1] += a4.y * w4.x;
            acc[0][2] += a4.z * w4.x; acc[0][3] += a4.w * w4.x;
            acc[1][0] += a4.x * w4.y; acc[1][1] += a4.y * w4.y;
            acc[1][2] += a4.z * w4.y; acc[1][3] += a4.w * w4.y;
            acc[2][0] += a4.x * w4.z; acc[2][1] += a4.y * w4.z;
            acc[2][2] += a4.z * w4.z; acc[2][3] += a4.w * w4.z;
            acc[3][0] += a4.x * w4.w; acc[3][1] += a4.y * w4.w;
            acc[3][2] += a4.z * w4.w; acc[3][3] += a4.w * w4.w;
        }
        __syncthreads();
    }

    // Store xz[t][c][b-quad] + bias
    #pragma unroll
    for (int jj = 0; jj < 4; jj++) {
        const int c  = c0 + tc * 4 + jj;
        const float bv = bias[c];
        float4 v = make_float4(acc[jj][0] + bv, acc[jj][1] + bv,
                               acc[jj][2] + bv, acc[jj][3] + bv);
        *(float4*)&g_xz[(size_t)t * (G4 * BB) + (size_t)c * BB + tb * 4] = v;
    }
}

// ---------------------------------------------------------------------------
// Kernel 2: persistent LSTM recurrence.
// 128 blocks x 128 threads. Block bid owns u-slice u0..u0+3 (all 4 gates ->
// c/h update is thread-local). Thread (warp j, lane) owns (u0+j, b=2*lane,
// b=2*lane+1). Dynamic smem: h_sm[512][64] (128KB) + w_sm[512][4][4] (32KB).
// ---------------------------------------------------------------------------
__device__ __forceinline__ float sigf(float x) {
    return 1.0f / (1.0f + expf(-x));
}

__global__ void __launch_bounds__(RTHREADS, 1) lstm_kernel(
        const float* __restrict__ rk /* [512][2048] */) {
    extern __shared__ float smem[];
    float* h_sm = smem;              // 512*64
    float* w_sm = smem + UU * BB;    // 512*16 : [k][j][g]

    const int tid  = threadIdx.x;
    const int lane = tid & 31;
    const int j    = tid >> 5;       // 0..3 (warp id = u offset)
    const int u0   = blockIdx.x * 4;
    const int u    = u0 + j;

    // Stage recurrent weight slice: w_sm[k][jj][g] = rk[k][g*512 + u0 + jj]
    for (int idx = tid; idx < UU * 16; idx += RTHREADS) {
        const int k = idx >> 4, jg = idx & 15, jj = jg >> 2, g = jg & 3;
        w_sm[idx] = rk[(size_t)k * G4 + g * UU + u0 + jj];
    }
    // Zero our slice of h buffer 0 (h0 = 0)
    for (int idx = tid; idx < 4 * BB; idx += RTHREADS)
        g_hT[0][u0 * BB + idx] = 0.f;

    float c0v = 0.f, c1v = 0.f;
    grid_barrier(gridDim.x);   // h0 fully zeroed, weights staged

    for (int t = 0; t < TT; t++) {
        // Stage full h (prev step) into smem. .cg: bypass (possibly stale) L1.
        {
            const float4* src = (const float4*)g_hT[t % 3];
            float4* dst = (float4*)h_sm;
            for (int i = tid; i < (UU * BB) / 4; i += RTHREADS)
                dst[i] = __ldcg(src + i);
        }
        __syncthreads();

        // z init from precomputed xz (includes bias)
        const float* xzt = g_xz + (size_t)t * (G4 * BB);
        float acc[8];   // [g][b01]
        #pragma unroll
        for (int g = 0; g < 4; g++) {
            const float2 v = *(const float2*)(xzt + (size_t)(g * UU + u) * BB + 2 * lane);
            acc[g * 2]     = v.x;
            acc[g * 2 + 1] = v.y;
        }

        // z += h @ W_rec  (h broadcast over warps, W broadcast over lanes)
        const float* hp = h_sm + 2 * lane;
        const float* wp = w_sm + j * 4;
        #pragma unroll 4
        for (int k = 0; k < UU; k++) {
            const float2 h2 = *(const float2*)(hp + k * BB);
            const float4 w4 = *(const float4*)(wp + k * 16);
            acc[0] += h2.x * w4.x; acc[1] += h2.y * w4.x;
            acc[2] += h2.x * w4.y; acc[3] += h2.y * w4.y;
            acc[4] += h2.x * w4.z; acc[5] += h2.y * w4.z;
            acc[6] += h2.x * w4.w; acc[7] += h2.y * w4.w;
        }

        // Gates: v1=tanh(z1) v2=sig(z2) v3=sig(z3) v4=sig(z4)
        const float v1a = tanhf(acc[0]), v1b = tanhf(acc[1]);
        const float v2a = sigf(acc[2]),  v2b = sigf(acc[3]);
        const float v3a = sigf(acc[4]),  v3b = sigf(acc[5]);
        const float v4a = sigf(acc[6]),  v4b = sigf(acc[7]);
        c0v = v1a * v2a + v3a * c0v;
        c1v = v1b * v2b + v3b * c1v;
        const float h0 = v4a * tanhf(c0v);
        const float h1 = v4b * tanhf(c1v);

        // Publish new h slice (next buffer)
        *(float2*)(g_hT[(t + 1) % 3] + (size_t)u * BB + 2 * lane) =
            make_float2(h0, h1);

        grid_barrier(gridDim.x);   // includes threadfence; all writes visible
    }
}

// ---------------------------------------------------------------------------
// Kernel 3: out = softmax(h_last @ fc_w + fc_b). h_last lives in g_hT[TT%3].
// ---------------------------------------------------------------------------
__global__ void head_kernel(const float* __restrict__ fc_w,
                            const float* __restrict__ fc_b,
                            float* __restrict__ out) {
    const int b = threadIdx.x;   // 64 threads
    const float* h = g_hT[TT % 3];   // 1024 % 3 == 1
    float a0 = fc_b[0], a1 = fc_b[1], a2 = fc_b[2], a3 = fc_b[3];
    for (int u = 0; u < UU; u++) {
        const float hv = h[u * BB + b];
        const float4 w = *(const float4*)(fc_w + u * 4);
        a0 += hv * w.x; a1 += hv * w.y; a2 += hv * w.z; a3 += hv * w.w;
    }
    const float m = fmaxf(fmaxf(a0, a1), fmaxf(a2, a3));
    const float e0 = expf(a0 - m), e1 = expf(a1 - m);
    const float e2 = expf(a2 - m), e3 = expf(a3 - m);
    const float s = e0 + e1 + e2 + e3;
    out[b * 4 + 0] = e0 / s;
    out[b * 4 + 1] = e1 / s;
    out[b * 4 + 2] = e2 / s;
    out[b * 4 + 3] = e3 / s;
}

// ---------------------------------------------------------------------------
// Launch
// ---------------------------------------------------------------------------
extern "C" void kernel_launch(void* const* d_in, const int* in_sizes, int n_in,
                              void* d_out, int out_size) {
    const float* tx   = (const float*)d_in[0];
    const float* wk   = (const float*)d_in[1];
    const float* rk   = (const float*)d_in[2];
    const float* bias = (const float*)d_in[3];
    const float* fc_w = (const float*)d_in[4];
    const float* fc_b = (const float*)d_in[5];
    float* out = (float*)d_out;

    const int smem_bytes = (UU * BB + UU * 16) * (int)sizeof(float);  // 163840
    cudaFuncSetAttribute(lstm_kernel,
                         cudaFuncAttributeMaxDynamicSharedMemorySize, smem_bytes);

    dim3 g1(G4 / 64, TT);
    xz_gemm_kernel<<<g1, 256>>>(tx, wk, bias);
    lstm_kernel<<<RBLOCKS, RTHREADS, smem_bytes>>>(rk);
    head_kernel<<<1, BB>>>(fc_w, fc_b, out);
}

// round 2
// speedup vs baseline: 1.0576x; 1.0576x over previous
#include <cuda_runtime.h>
#include <math.h>
#include <stdint.h>

// Problem dims
#define BB   64
#define TT   1024
#define DD   512
#define UU   512
#define G4   2048   // 4*U
#define NOUT 4

#define RBLOCKS  128
#define RTHREADS 128

typedef unsigned long long ull;

// ---------------------------------------------------------------------------
// Packed fp32 helpers (fma.rn.f32x2 — PTX-only, 2x FFMA throughput)
// ---------------------------------------------------------------------------
__device__ __forceinline__ ull ffma2(ull a, ull b, ull c) {
    ull d;
    asm("fma.rn.f32x2 %0, %1, %2, %3;" : "=l"(d) : "l"(a), "l"(b), "l"(c));
    return d;
}
__device__ __forceinline__ ull pack2(float x, float y) {
    ull r;
    asm("mov.b64 %0, {%1, %2};" : "=l"(r) : "f"(x), "f"(y));
    return r;
}
__device__ __forceinline__ float2 unpack2(ull v) {
    float2 f;
    asm("mov.b64 {%0, %1}, %2;" : "=f"(f.x), "=f"(f.y) : "l"(v));
    return f;
}
__device__ __forceinline__ void cpasync16(uint32_t saddr, const void* gptr) {
    asm volatile("cp.async.cg.shared.global [%0], [%1], 16;"
                 :: "r"(saddr), "l"(gptr));
}

// ---------------------------------------------------------------------------
// Scratch (static device memory only)
// ---------------------------------------------------------------------------
__device__ float g_xz[(size_t)TT * G4 * BB];   // [t][col][b], 512MB
__device__ float g_hT[3][UU * BB];             // h transposed [u][b], 3 buffers
__device__ unsigned g_bar_arrive;
__device__ unsigned g_bar_gen;

// ---------------------------------------------------------------------------
// Software grid barrier (all RBLOCKS CTAs co-resident: 160KB smem -> 1/SM)
// ---------------------------------------------------------------------------
__device__ __forceinline__ void grid_barrier(unsigned nb) {
    __syncthreads();
    if (threadIdx.x == 0) {
        __threadfence();
        unsigned gen = atomicAdd(&g_bar_gen, 0u);
        if (atomicAdd(&g_bar_arrive, 1u) == nb - 1u) {
            atomicExch(&g_bar_arrive, 0u);
            __threadfence();
            atomicAdd(&g_bar_gen, 1u);
        } else {
            while (atomicAdd(&g_bar_gen, 0u) == gen) { __nanosleep(64); }
        }
        __threadfence();
    }
    __syncthreads();
}

// ---------------------------------------------------------------------------
// Kernel 1: xz[t][col][b] = sum_d tx[b][t][d] * kernel[d][col] + bias[col]
// Block tile 64b x 128c, K-tile 32. 256 threads, thread tile 4b x 8c, FFMA2.
// ---------------------------------------------------------------------------
__global__ void __launch_bounds__(256) xz_gemm_kernel(
        const float* __restrict__ tx,
        const float* __restrict__ wk,
        const float* __restrict__ bias) {
    __shared__ float a_s[32][68];    // [kk][b], 272B rows (16B aligned)
    __shared__ float w_s[32][128];   // [kk][c]

    const int t   = blockIdx.y;
    const int c0  = blockIdx.x * 128;
    const int tid = threadIdx.x;
    const int tb  = tid & 15;        // b-group: 4 b's
    const int tc  = tid >> 4;        // c-group: 8 c's

    ull acc[4][4];                   // [b][cpair], packed over 2 columns
    #pragma unroll
    for (int i = 0; i < 4; i++)
        #pragma unroll
        for (int j = 0; j < 4; j++) acc[i][j] = 0ull;

    for (int k0 = 0; k0 < DD; k0 += 32) {
        // A tile (transpose -> [kk][b]): thread loads 8 consecutive k of one b
        {
            const int b  = tid >> 2;
            const int kg = tid & 3;
            const float* src = tx + (size_t)b * (TT * DD) + (size_t)t * DD
                                  + k0 + kg * 8;
            const float4 v0 = *(const float4*)src;
            const float4 v1 = *(const float4*)(src + 4);
            a_s[kg * 8 + 0][b] = v0.x; a_s[kg * 8 + 1][b] = v0.y;
            a_s[kg * 8 + 2][b] = v0.z; a_s[kg * 8 + 3][b] = v0.w;
            a_s[kg * 8 + 4][b] = v1.x; a_s[kg * 8 + 5][b] = v1.y;
            a_s[kg * 8 + 6][b] = v1.z; a_s[kg * 8 + 7][b] = v1.w;
        }
        // W tile [kk][c]: coalesced float4
        #pragma unroll
        for (int i = 0; i < 4; i++) {
            const int idx = tid + i * 256;
            const int kk = idx >> 5, cc = (idx & 31) * 4;
            *(float4*)&w_s[kk][cc] =
                *(const float4*)&wk[(size_t)(k0 + kk) * G4 + c0 + cc];
        }
        __syncthreads();

        #pragma unroll
        for (int kk = 0; kk < 32; kk++) {
            const float4 a4 = *(const float4*)&a_s[kk][tb * 4];
            const ull a0 = pack2(a4.x, a4.x);
            const ull a1 = pack2(a4.y, a4.y);
            const ull a2 = pack2(a4.z, a4.z);
            const ull a3 = pack2(a4.w, a4.w);
            const ull* wp = (const ull*)&w_s[kk][tc * 8];   // 4 col-pairs
            const ull w0 = wp[0], w1 = wp[1], w2 = wp[2], w3 = wp[3];
            acc[0][0] = ffma2(a0, w0, acc[0][0]);
            acc[1][0] = ffma2(a1, w0, acc[1][0]);
            acc[2][0] = ffma2(a2, w0, acc[2][0]);
            acc[3][0] = ffma2(a3, w0, acc[3][0]);
            acc[0][1] = ffma2(a0, w1, acc[0][1]);
            acc[1][1] = ffma2(a1, w1, acc[1][1]);
            acc[2][1] = ffma2(a2, w1, acc[2][1]);
            acc[3][1] = ffma2(a3, w1, acc[3][1]);
            acc[0][2] = ffma2(a0, w2, acc[0][2]);
            acc[1][2] = ffma2(a1, w2, acc[1][2]);
            acc[2][2] = ffma2(a2, w2, acc[2][2]);
            acc[3][2] = ffma2(a3, w2, acc[3][2]);
            acc[0][3] = ffma2(a0, w3, acc[0][3]);
            acc[1][3] = ffma2(a1, w3, acc[1][3]);
            acc[2][3] = ffma2(a2, w3, acc[2][3]);
            acc[3][3] = ffma2(a3, w3, acc[3][3]);
        }
        __syncthreads();
    }

    // Epilogue: unpack + bias, store xz[t][c][4b] as float4
    #pragma unroll
    for (int j = 0; j < 4; j++) {       // column pair
        float2 r0 = unpack2(acc[0][j]);
        float2 r1 = unpack2(acc[1][j]);
        float2 r2 = unpack2(acc[2][j]);
        float2 r3 = unpack2(acc[3][j]);
        #pragma unroll
        for (int s = 0; s < 2; s++) {
            const int c = c0 + tc * 8 + j * 2 + s;
            const float bv = bias[c];
            float4 v;
            v.x = (s ? r0.y : r0.x) + bv;
            v.y = (s ? r1.y : r1.x) + bv;
            v.z = (s ? r2.y : r2.x) + bv;
            v.w = (s ? r3.y : r3.x) + bv;
            *(float4*)&g_xz[(size_t)t * (G4 * BB) + (size_t)c * BB + tb * 4] = v;
        }
    }
}

// ---------------------------------------------------------------------------
// Kernel 2: persistent LSTM recurrence, FFMA2 + cp.async-pipelined h staging.
// 128 blocks x 128 threads, 1 CTA/SM. Block owns 4 u's (16 cols).
// Thread: 1 batch b, 2 u's (a pair), all 4 gates.
//   warp w: b-half = w&1, u-pair = w>>1 ; lane -> b within half.
// smem: h_sm[512][64] (128KB) + w_sm[512][16] (32KB), 160KB total.
//   w_sm[k][up*8 + g*2 + j] = rk[k][g*512 + u0 + up*2 + j]  (packed u-pairs)
// ---------------------------------------------------------------------------
__device__ __forceinline__ float sigf(float x) {
    return 1.0f / (1.0f + expf(-x));
}

__global__ void __launch_bounds__(RTHREADS, 1) lstm_kernel(
        const float* __restrict__ rk /* [512][2048] */) {
    extern __shared__ float smem[];
    float* h_sm = smem;              // 512*64
    float* w_sm = smem + UU * BB;    // 512*16

    const int tid  = threadIdx.x;
    const int lane = tid & 31;
    const int wrp  = tid >> 5;
    const int b    = (wrp & 1) * 32 + lane;
    const int up   = wrp >> 1;                 // u-pair index 0..1
    const int u0   = blockIdx.x * 4;
    const int ua   = u0 + up * 2;              // first u of this thread's pair

    const uint32_t h_sm_u32 =
        (uint32_t)__cvta_generic_to_shared(h_sm);

    // Stage recurrent weights (interleaved u-pairs for packed FFMA2 operands)
    for (int idx = tid; idx < UU * 16; idx += RTHREADS) {
        const int k = idx >> 4, r = idx & 15;
        const int up_ = r >> 3, g = (r >> 1) & 3, j = r & 1;
        w_sm[idx] = rk[(size_t)k * G4 + g * UU + u0 + up_ * 2 + j];
    }
    // Zero our slice of h buffer 0
    for (int idx = tid; idx < 4 * BB; idx += RTHREADS)
        g_hT[0][u0 * BB + idx] = 0.f;

    float ca = 0.f, cb = 0.f;       // cell states for the 2 u's
    grid_barrier(gridDim.x);

    for (int t = 0; t < TT; t++) {
        // ---- issue pipelined h staging: 4 chunks x 128 k-rows (32KB each)
        const float* hsrc = g_hT[t % 3];
        #pragma unroll
        for (int ch = 0; ch < 4; ch++) {
            const float4* src = (const float4*)(hsrc + ch * 128 * BB);
            const uint32_t dst = h_sm_u32 + ch * 128 * BB * 4;
            #pragma unroll
            for (int i = 0; i < 16; i++) {
                const int e = tid + i * RTHREADS;   // 2048 float4 per chunk
                cpasync16(dst + e * 16, src + e);
            }
            asm volatile("cp.async.commit_group;");
        }

        // ---- init z from precomputed xz (includes bias); packed over u-pair
        const float* xzt = g_xz + (size_t)t * (G4 * BB);
        ull acc[4];
        #pragma unroll
        for (int g = 0; g < 4; g++) {
            const float za = xzt[(size_t)(g * UU + ua)     * BB + b];
            const float zb = xzt[(size_t)(g * UU + ua + 1) * BB + b];
            acc[g] = pack2(za, zb);
        }

        // ---- z += h @ W_rec, chunked to overlap with cp.async
        #pragma unroll
        for (int ch = 0; ch < 4; ch++) {
            if (ch == 0)      asm volatile("cp.async.wait_group 3;");
            else if (ch == 1) asm volatile("cp.async.wait_group 2;");
            else if (ch == 2) asm volatile("cp.async.wait_group 1;");
            else              asm volatile("cp.async.wait_group 0;");
            __syncthreads();

            const float* hp = h_sm + ch * 128 * BB + b;
            const float* wp = w_sm + ch * 128 * 16 + up * 8;
            #pragma unroll 4
            for (int k = 0; k < 128; k++) {
                const float hv = hp[k * BB];
                const ull h2 = pack2(hv, hv);
                const ull* w2 = (const ull*)(wp + k * 16);
                acc[0] = ffma2(h2, w2[0], acc[0]);
                acc[1] = ffma2(h2, w2[1], acc[1]);
                acc[2] = ffma2(h2, w2[2], acc[2]);
                acc[3] = ffma2(h2, w2[3], acc[3]);
            }
        }

        // ---- gates + state update for both u's
        const float2 z1 = unpack2(acc[0]);
        const float2 z2 = unpack2(acc[1]);
        const float2 z3 = unpack2(acc[2]);
        const float2 z4 = unpack2(acc[3]);
        const float v1a = tanhf(z1.x), v1b = tanhf(z1.y);
        const float v2a = sigf(z2.x),  v2b = sigf(z2.y);
        const float v3a = sigf(z3.x),  v3b = sigf(z3.y);
        const float v4a = sigf(z4.x),  v4b = sigf(z4.y);
        ca = v1a * v2a + v3a * ca;
        cb = v1b * v2b + v3b * cb;
        const float ha = v4a * tanhf(ca);
        const float hb = v4b * tanhf(cb);

        // ---- publish new h slice (next buffer)
        float* hdst = g_hT[(t + 1) % 3];
        hdst[(size_t)ua       * BB + b] = ha;
        hdst[(size_t)(ua + 1) * BB + b] = hb;

        grid_barrier(gridDim.x);
    }
}

// ---------------------------------------------------------------------------
// Kernel 3: out = softmax(h_last @ fc_w + fc_b). h_last in g_hT[TT%3]=[1].
// ---------------------------------------------------------------------------
__global__ void head_kernel(const float* __restrict__ fc_w,
                            const float* __restrict__ fc_b,
                            float* __restrict__ out) {
    const int b = threadIdx.x;   // 64 threads
    const float* h = g_hT[TT % 3];
    float a0 = fc_b[0], a1 = fc_b[1], a2 = fc_b[2], a3 = fc_b[3];
    for (int u = 0; u < UU; u++) {
        const float hv = h[u * BB + b];
        const float4 w = *(const float4*)(fc_w + u * 4);
        a0 += hv * w.x; a1 += hv * w.y; a2 += hv * w.z; a3 += hv * w.w;
    }
    const float m = fmaxf(fmaxf(a0, a1), fmaxf(a2, a3));
    const float e0 = expf(a0 - m), e1 = expf(a1 - m);
    const float e2 = expf(a2 - m), e3 = expf(a3 - m);
    const float s = e0 + e1 + e2 + e3;
    out[b * 4 + 0] = e0 / s;
    out[b * 4 + 1] = e1 / s;
    out[b * 4 + 2] = e2 / s;
    out[b * 4 + 3] = e3 / s;
}

// ---------------------------------------------------------------------------
// Launch
// ---------------------------------------------------------------------------
extern "C" void kernel_launch(void* const* d_in, const int* in_sizes, int n_in,
                              void* d_out, int out_size) {
    const float* tx   = (const float*)d_in[0];
    const float* wk   = (const float*)d_in[1];
    const float* rk   = (const float*)d_in[2];
    const float* bias = (const float*)d_in[3];
    const float* fc_w = (const float*)d_in[4];
    const float* fc_b = (const float*)d_in[5];
    float* out = (float*)d_out;

    const int smem_bytes = (UU * BB + UU * 16) * (int)sizeof(float);  // 163840
    cudaFuncSetAttribute(lstm_kernel,
                         cudaFuncAttributeMaxDynamicSharedMemorySize, smem_bytes);

    dim3 g1(G4 / 128, TT);
    xz_gemm_kernel<<<g1, 256>>>(tx, wk, bias);
    lstm_kernel<<<RBLOCKS, RTHREADS, smem_bytes>>>(rk);
    head_kernel<<<1, BB>>>(fc_w, fc_b, out);
}

// round 4
// speedup vs baseline: 1.0584x; 1.0007x over previous
#include <cuda_runtime.h>
#include <math.h>
#include <stdint.h>

// Problem dims
#define BB   64
#define TT   1024
#define DD   512
#define UU   512
#define G4   2048   // 4*U
#define NOUT 4

#define RBLOCKS  128
#define RTHREADS 128

typedef unsigned long long ull;

// ---------------------------------------------------------------------------
// Packed fp32 helpers (fma.rn.f32x2 — PTX-only, 2x FFMA throughput)
// ---------------------------------------------------------------------------
__device__ __forceinline__ ull ffma2(ull a, ull b, ull c) {
    ull d;
    asm("fma.rn.f32x2 %0, %1, %2, %3;" : "=l"(d) : "l"(a), "l"(b), "l"(c));
    return d;
}
__device__ __forceinline__ ull pack2(float x, float y) {
    ull r;
    asm("mov.b64 %0, {%1, %2};" : "=l"(r) : "f"(x), "f"(y));
    return r;
}
__device__ __forceinline__ float2 unpack2(ull v) {
    float2 f;
    asm("mov.b64 {%0, %1}, %2;" : "=f"(f.x), "=f"(f.y) : "l"(v));
    return f;
}
__device__ __forceinline__ void cpasync16(uint32_t saddr, const void* gptr) {
    asm volatile("cp.async.cg.shared.global [%0], [%1], 16;"
                 :: "r"(saddr), "l"(gptr));
}

// ---------------------------------------------------------------------------
// Scratch (static device memory only)
// ---------------------------------------------------------------------------
__device__ float g_xz[(size_t)TT * G4 * BB];   // [t][col][b], 512MB
__device__ float g_hT[3][UU * BB];             // h transposed [u][b], 3 buffers
__device__ unsigned g_bar_arrive;
__device__ unsigned g_bar_gen;

// ---------------------------------------------------------------------------
// Software grid barrier (all RBLOCKS CTAs co-resident: 160KB smem -> 1/SM)
// ---------------------------------------------------------------------------
__device__ __forceinline__ void grid_barrier(unsigned nb) {
    __syncthreads();
    if (threadIdx.x == 0) {
        __threadfence();
        unsigned gen = atomicAdd(&g_bar_gen, 0u);
        if (atomicAdd(&g_bar_arrive, 1u) == nb - 1u) {
            atomicExch(&g_bar_arrive, 0u);
            __threadfence();
            atomicAdd(&g_bar_gen, 1u);
        } else {
            while (atomicAdd(&g_bar_gen, 0u) == gen) { __nanosleep(64); }
        }
        __threadfence();
    }
    __syncthreads();
}

// ---------------------------------------------------------------------------
// Kernel 1: xz[t][col][b] = sum_d tx[b][t][d] * kernel[d][col] + bias[col]
// Block tile 64b x 128c, K-tile 32. 256 threads, thread tile 4b x 8c, FFMA2.
// ---------------------------------------------------------------------------
__global__ void __launch_bounds__(256) xz_gemm_kernel(
        const float* __restrict__ tx,
        const float* __restrict__ wk,
        const float* __restrict__ bias) {
    __shared__ float a_s[32][68];    // [kk][b], 272B rows (16B aligned)
    __shared__ float w_s[32][128];   // [kk][c]

    const int t   = blockIdx.y;
    const int c0  = blockIdx.x * 128;
    const int tid = threadIdx.x;
    const int tb  = tid & 15;        // b-group: 4 b's
    const int tc  = tid >> 4;        // c-group: 8 c's

    ull acc[4][4];                   // [b][cpair], packed over 2 columns
    #pragma unroll
    for (int i = 0; i < 4; i++)
        #pragma unroll
        for (int j = 0; j < 4; j++) acc[i][j] = 0ull;

    for (int k0 = 0; k0 < DD; k0 += 32) {
        // A tile (transpose -> [kk][b]): thread loads 8 consecutive k of one b
        {
            const int b  = tid >> 2;
            const int kg = tid & 3;
            const float* src = tx + (size_t)b * (TT * DD) + (size_t)t * DD
                                  + k0 + kg * 8;
            const float4 v0 = *(const float4*)src;
            const float4 v1 = *(const float4*)(src + 4);
            a_s[kg * 8 + 0][b] = v0.x; a_s[kg * 8 + 1][b] = v0.y;
            a_s[kg * 8 + 2][b] = v0.z; a_s[kg * 8 + 3][b] = v0.w;
            a_s[kg * 8 + 4][b] = v1.x; a_s[kg * 8 + 5][b] = v1.y;
            a_s[kg * 8 + 6][b] = v1.z; a_s[kg * 8 + 7][b] = v1.w;
        }
        // W tile [kk][c]: coalesced float4
        #pragma unroll
        for (int i = 0; i < 4; i++) {
            const int idx = tid + i * 256;
            const int kk = idx >> 5, cc = (idx & 31) * 4;
            *(float4*)&w_s[kk][cc] =
                *(const float4*)&wk[(size_t)(k0 + kk) * G4 + c0 + cc];
        }
        __syncthreads();

        #pragma unroll
        for (int kk = 0; kk < 32; kk++) {
            const float4 a4 = *(const float4*)&a_s[kk][tb * 4];
            const ull a0 = pack2(a4.x, a4.x);
            const ull a1 = pack2(a4.y, a4.y);
            const ull a2 = pack2(a4.z, a4.z);
            const ull a3 = pack2(a4.w, a4.w);
            const ull* wp = (const ull*)&w_s[kk][tc * 8];   // 4 col-pairs
            const ull w0 = wp[0], w1 = wp[1], w2 = wp[2], w3 = wp[3];
            acc[0][0] = ffma2(a0, w0, acc[0][0]);
            acc[1][0] = ffma2(a1, w0, acc[1][0]);
            acc[2][0] = ffma2(a2, w0, acc[2][0]);
            acc[3][0] = ffma2(a3, w0, acc[3][0]);
            acc[0][1] = ffma2(a0, w1, acc[0][1]);
            acc[1][1] = ffma2(a1, w1, acc[1][1]);
            acc[2][1] = ffma2(a2, w1, acc[2][1]);
            acc[3][1] = ffma2(a3, w1, acc[3][1]);
            acc[0][2] = ffma2(a0, w2, acc[0][2]);
            acc[1][2] = ffma2(a1, w2, acc[1][2]);
            acc[2][2] = ffma2(a2, w2, acc[2][2]);
            acc[3][2] = ffma2(a3, w2, acc[3][2]);
            acc[0][3] = ffma2(a0, w3, acc[0][3]);
            acc[1][3] = ffma2(a1, w3, acc[1][3]);
            acc[2][3] = ffma2(a2, w3, acc[2][3]);
            acc[3][3] = ffma2(a3, w3, acc[3][3]);
        }
        __syncthreads();
    }

    // Epilogue: unpack + bias, store xz[t][c][4b] as float4
    #pragma unroll
    for (int j = 0; j < 4; j++) {       // column pair
        float2 r0 = unpack2(acc[0][j]);
        float2 r1 = unpack2(acc[1][j]);
        float2 r2 = unpack2(acc[2][j]);
        float2 r3 = unpack2(acc[3][j]);
        #pragma unroll
        for (int s = 0; s < 2; s++) {
            const int c = c0 + tc * 8 + j * 2 + s;
            const float bv = bias[c];
            float4 v;
            v.x = (s ? r0.y : r0.x) + bv;
            v.y = (s ? r1.y : r1.x) + bv;
            v.z = (s ? r2.y : r2.x) + bv;
            v.w = (s ? r3.y : r3.x) + bv;
            *(float4*)&g_xz[(size_t)t * (G4 * BB) + (size_t)c * BB + tb * 4] = v;
        }
    }
}

// ---------------------------------------------------------------------------
// Kernel 2: persistent LSTM recurrence, FFMA2 + cp.async-pipelined h staging.
// 128 blocks x 128 threads, 1 CTA/SM. Block owns 4 u's (16 cols).
// Thread: 1 batch b, 2 u's (a pair), all 4 gates.
//   warp w: b-half = w&1, u-pair = w>>1 ; lane -> b within half.
// smem: h_sm[512][64] (128KB) + w_sm[512][16] (32KB), 160KB total.
//   w_sm[k][up*8 + g*2 + j] = rk[k][g*512 + u0 + up*2 + j]  (packed u-pairs)
// ---------------------------------------------------------------------------
__device__ __forceinline__ float sigf(float x) {
    return 1.0f / (1.0f + expf(-x));
}

__global__ void __launch_bounds__(RTHREADS, 1) lstm_kernel(
        const float* __restrict__ rk /* [512][2048] */) {
    extern __shared__ float smem[];
    float* h_sm = smem;              // 512*64
    float* w_sm = smem + UU * BB;    // 512*16

    const int tid  = threadIdx.x;
    const int lane = tid & 31;
    const int wrp  = tid >> 5;
    const int b    = (wrp & 1) * 32 + lane;
    const int up   = wrp >> 1;                 // u-pair index 0..1
    const int u0   = blockIdx.x * 4;
    const int ua   = u0 + up * 2;              // first u of this thread's pair

    const uint32_t h_sm_u32 =
        (uint32_t)__cvta_generic_to_shared(h_sm);

    // Stage recurrent weights (interleaved u-pairs for packed FFMA2 operands)
    for (int idx = tid; idx < UU * 16; idx += RTHREADS) {
        const int k = idx >> 4, r = idx & 15;
        const int up_ = r >> 3, g = (r >> 1) & 3, j = r & 1;
        w_sm[idx] = rk[(size_t)k * G4 + g * UU + u0 + up_ * 2 + j];
    }
    // Zero our slice of h buffer 0
    for (int idx = tid; idx < 4 * BB; idx += RTHREADS)
        g_hT[0][u0 * BB + idx] = 0.f;

    float ca = 0.f, cb = 0.f;       // cell states for the 2 u's
    grid_barrier(gridDim.x);

    for (int t = 0; t < TT; t++) {
        // ---- issue pipelined h staging: 4 chunks x 128 k-rows (32KB each)
        const float* hsrc = g_hT[t % 3];
        #pragma unroll
        for (int ch = 0; ch < 4; ch++) {
            const float4* src = (const float4*)(hsrc + ch * 128 * BB);
            const uint32_t dst = h_sm_u32 + ch * 128 * BB * 4;
            #pragma unroll
            for (int i = 0; i < 16; i++) {
                const int e = tid + i * RTHREADS;   // 2048 float4 per chunk
                cpasync16(dst + e * 16, src + e);
            }
            asm volatile("cp.async.commit_group;");
        }

        // ---- init z from precomputed xz (includes bias); packed over u-pair
        const float* xzt = g_xz + (size_t)t * (G4 * BB);
        ull acc[4];
        #pragma unroll
        for (int g = 0; g < 4; g++) {
            const float za = xzt[(size_t)(g * UU + ua)     * BB + b];
            const float zb = xzt[(size_t)(g * UU + ua + 1) * BB + b];
            acc[g] = pack2(za, zb);
        }

        // ---- z += h @ W_rec, chunked to overlap with cp.async
        #pragma unroll
        for (int ch = 0; ch < 4; ch++) {
            if (ch == 0)      asm volatile("cp.async.wait_group 3;");
            else if (ch == 1) asm volatile("cp.async.wait_group 2;");
            else if (ch == 2) asm volatile("cp.async.wait_group 1;");
            else              asm volatile("cp.async.wait_group 0;");
            __syncthreads();

            const float* hp = h_sm + ch * 128 * BB + b;
            const float* wp = w_sm + ch * 128 * 16 + up * 8;
            #pragma unroll 4
            for (int k = 0; k < 128; k++) {
                const float hv = hp[k * BB];
                const ull h2 = pack2(hv, hv);
                const ull* w2 = (const ull*)(wp + k * 16);
                acc[0] = ffma2(h2, w2[0], acc[0]);
                acc[1] = ffma2(h2, w2[1], acc[1]);
                acc[2] = ffma2(h2, w2[2], acc[2]);
                acc[3] = ffma2(h2, w2[3], acc[3]);
            }
        }

        // ---- gates + state update for both u's
        const float2 z1 = unpack2(acc[0]);
        const float2 z2 = unpack2(acc[1]);
        const float2 z3 = unpack2(acc[2]);
        const float2 z4 = unpack2(acc[3]);
        const float v1a = tanhf(z1.x), v1b = tanhf(z1.y);
        const float v2a = sigf(z2.x),  v2b = sigf(z2.y);
        const float v3a = sigf(z3.x),  v3b = sigf(z3.y);
        const float v4a = sigf(z4.x),  v4b = sigf(z4.y);
        ca = v1a * v2a + v3a * ca;
        cb = v1b * v2b + v3b * cb;
        const float ha = v4a * tanhf(ca);
        const float hb = v4b * tanhf(cb);

        // ---- publish new h slice (next buffer)
        float* hdst = g_hT[(t + 1) % 3];
        hdst[(size_t)ua       * BB + b] = ha;
        hdst[(size_t)(ua + 1) * BB + b] = hb;

        grid_barrier(gridDim.x);
    }
}

// ---------------------------------------------------------------------------
// Kernel 3: out = softmax(h_last @ fc_w + fc_b). h_last in g_hT[TT%3]=[1].
// ---------------------------------------------------------------------------
__global__ void head_kernel(const float* __restrict__ fc_w,
                            const float* __restrict__ fc_b,
                            float* __restrict__ out) {
    const int b = threadIdx.x;   // 64 threads
    const float* h = g_hT[TT % 3];
    float a0 = fc_b[0], a1 = fc_b[1], a2 = fc_b[2], a3 = fc_b[3];
    for (int u = 0; u < UU; u++) {
        const float hv = h[u * BB + b];
        const float4 w = *(const float4*)(fc_w + u * 4);
        a0 += hv * w.x; a1 += hv * w.y; a2 += hv * w.z; a3 += hv * w.w;
    }
    const float m = fmaxf(fmaxf(a0, a1), fmaxf(a2, a3));
    const float e0 = expf(a0 - m), e1 = expf(a1 - m);
    const float e2 = expf(a2 - m), e3 = expf(a3 - m);
    const float s = e0 + e1 + e2 + e3;
    out[b * 4 + 0] = e0 / s;
    out[b * 4 + 1] = e1 / s;
    out[b * 4 + 2] = e2 / s;
    out[b * 4 + 3] = e3 / s;
}

// ---------------------------------------------------------------------------
// Launch
// ---------------------------------------------------------------------------
extern "C" void kernel_launch(void* const* d_in, const int* in_sizes, int n_in,
                              void* d_out, int out_size) {
    const float* tx   = (const float*)d_in[0];
    const float* wk   = (const float*)d_in[1];
    const float* rk   = (const float*)d_in[2];
    const float* bias = (const float*)d_in[3];
    const float* fc_w = (const float*)d_in[4];
    const float* fc_b = (const float*)d_in[5];
    float* out = (float*)d_out;

    const int smem_bytes = (UU * BB + UU * 16) * (int)sizeof(float);  // 163840
    cudaFuncSetAttribute(lstm_kernel,
                         cudaFuncAttributeMaxDynamicSharedMemorySize, smem_bytes);

    dim3 g1(G4 / 128, TT);
    xz_gemm_kernel<<<g1, 256>>>(tx, wk, bias);
    lstm_kernel<<<RBLOCKS, RTHREADS, smem_bytes>>>(rk);
    head_kernel<<<1, BB>>>(fc_w, fc_b, out);
}